// round 6
// baseline (speedup 1.0000x reference)
#include <cuda_runtime.h>
#include <cuda_fp16.h>
#include <mma.h>
using namespace nvcuda;

#define CCH 64
#define HH 120
#define WW 120
#define NBOX 4096
#define NPIX (HH*WW)
#define NSAMP 179      // 9 + 49 + 121
#define NTILE 450      // NPIX / 32

__device__ __half g_fm_h[NPIX * CCH];       // fp16 HWC feature map
__device__ float  g_part[NTILE * CCH];      // per-tile channel partial sums
__device__ __half g_gh_h[CCH];              // global-branch head output (fp16)

// padded fp16 weights (conflict-free ldm)
__device__ __half g_w1h[64 * 136];
__device__ __half g_w2h[128 * 72];
__device__ __half g_p1h[256 * 136];
__device__ __half g_p2h[128 * 72];

// ---------------------------------------------------------------- transpose CHW fp32 -> HWC fp16 (+ channel partial sums)
__global__ void k_transpose(const float* __restrict__ fm) {
    __shared__ float s[64][33];
    int tx = threadIdx.x, ty = threadIdx.y;          // (32, 8)
    int pix0 = blockIdx.x * 32;
    #pragma unroll
    for (int c = ty; c < 64; c += 8)
        s[c][tx] = fm[c * NPIX + pix0 + tx];
    __syncthreads();
    int t = ty * 32 + tx;
    int p = t >> 3;
    int c0 = (t & 7) * 8;
    __half h[8];
    #pragma unroll
    for (int k = 0; k < 8; k++) h[k] = __float2half_rn(s[c0 + k][p]);
    *reinterpret_cast<uint4*>(&g_fm_h[(pix0 + p) * 64 + c0]) = *reinterpret_cast<uint4*>(h);
    int c = t >> 2, q = t & 3;
    float v = 0.f;
    #pragma unroll
    for (int j = 0; j < 8; j++) v += s[c][q * 8 + j];
    v += __shfl_xor_sync(0xffffffffu, v, 1);
    v += __shfl_xor_sync(0xffffffffu, v, 2);
    if (q == 0) g_part[blockIdx.x * 64 + c] = v;
}

// ---------------------------------------------------------------- prep: weight convert (blocks 1..64) + global head (block 0)
__global__ void __launch_bounds__(512)
k_prep(const float* __restrict__ w1, const float* __restrict__ b1,
       const float* __restrict__ w2, const float* __restrict__ b2,
       const float* __restrict__ p1, const float* __restrict__ p2) {
    int t = threadIdx.x;
    if (blockIdx.x > 0) {
        int tid = (blockIdx.x - 1) * 512 + t;
        const int nt = 64 * 512;
        for (int i = tid; i < 8192; i += nt)  g_w1h[(i >> 7) * 136 + (i & 127)] = __float2half_rn(w1[i]);
        for (int i = tid; i < 8192; i += nt)  g_w2h[(i >> 6) * 72  + (i & 63)]  = __float2half_rn(w2[i]);
        for (int i = tid; i < 32768; i += nt) g_p1h[(i >> 7) * 136 + (i & 127)] = __float2half_rn(p1[i]);
        for (int i = tid; i < 8192; i += nt)  g_p2h[(i >> 6) * 72  + (i & 63)]  = __float2half_rn(p2[i]);
        return;
    }
    // block 0: global-mean shared head with wide ILP
    __shared__ float red[512];
    __shared__ float gs[64];
    __shared__ float hs[128];
    {
        int c = t & 63, g = t >> 6;                  // 8 groups
        float a0 = 0.f, a1 = 0.f, a2 = 0.f, a3 = 0.f;
        int bb = g;
        for (; bb + 24 < NTILE; bb += 32) {
            a0 += g_part[(bb     ) * 64 + c];
            a1 += g_part[(bb +  8) * 64 + c];
            a2 += g_part[(bb + 16) * 64 + c];
            a3 += g_part[(bb + 24) * 64 + c];
        }
        for (; bb < NTILE; bb += 8) a0 += g_part[bb * 64 + c];
        red[t] = (a0 + a1) + (a2 + a3);
    }
    __syncthreads();
    if (t < 64) {
        float s = 0.f;
        #pragma unroll
        for (int q = 0; q < 8; q++) s += red[t + 64 * q];
        gs[t] = s * (1.0f / (float)NPIX);
    }
    __syncthreads();
    {   // layer 1: 128 neurons x 4 threads (16 k each)
        int n = t >> 2, part = t & 3;
        float a = 0.f;
        int k0 = part * 16;
        #pragma unroll
        for (int k = 0; k < 16; k++) a = fmaf(gs[k0 + k], w1[(k0 + k) * 128 + n], a);
        red[t] = a;
    }
    __syncthreads();
    if (t < 128)
        hs[t] = fmaxf(red[t * 4] + red[t * 4 + 1] + red[t * 4 + 2] + red[t * 4 + 3] + b1[t], 0.f);
    __syncthreads();
    {   // layer 2: 64 neurons x 8 threads (16 k each)
        int n = t >> 3, part = t & 7;
        float a = 0.f;
        int k0 = part * 16;
        #pragma unroll
        for (int k = 0; k < 16; k++) a = fmaf(hs[k0 + k], w2[(k0 + k) * 64 + n], a);
        red[t] = a;
    }
    __syncthreads();
    if (t < 64) {
        float s = 0.f;
        #pragma unroll
        for (int q = 0; q < 8; q++) s += red[t * 8 + q];
        g_gh_h[t] = __float2half_rn(fmaxf(s + b2[t], 0.f));
    }
}

// ---------------------------------------------------------------- MEGA: pool(32 boxes x 3 scales) + head1 + final, per block
// smem layout (bytes):
//   w1h   @ 0        (17408)   64 x 136 h
//   w2h   @ 17408    (18432)   128 x 72 h
//   p1h   @ 35840    (69632)   256 x 136 h
//   p2h   @ 105472   (18432)   128 x 72 h
//   SEG1  @ 123904   (51968)   pool s_off/s_w+s_red -> h1f(96x132 f) -> c2f(96x68 f) -> h2f(32x132 f) -> c4f(32x68 f)
//   SEG2  @ 175872   (27008)   Ah(96x72 h) -> h1h(96x136 h) -> xh(32x264 h) -> h2h(32x136 h)
#define OFF_W1H 0
#define OFF_W2H 17408
#define OFF_P1H 35840
#define OFF_P2H 105472
#define OFF_SEG1 123904
#define OFF_SEG2 175872
#define SMEM_MEGA 202880

__global__ void __launch_bounds__(512, 1)
k_mega(const float* __restrict__ boxes,
       const float* __restrict__ b1, const float* __restrict__ b2,
       const float* __restrict__ pb1, const float* __restrict__ pb2,
       float* __restrict__ out) {
    extern __shared__ char smem[];
    __half* w1h = (__half*)(smem + OFF_W1H);
    __half* w2h = (__half*)(smem + OFF_W2H);
    __half* p1h = (__half*)(smem + OFF_P1H);
    __half* p2h = (__half*)(smem + OFF_P2H);

    int*    s_off = (int*)  (smem + OFF_SEG1);            // [8][4][179]
    float*  s_w   = (float*)(smem + OFF_SEG1 + 22912);    // [8][4][179]
    float4* s_red = (float4*)(smem + OFF_SEG1 + 45824);   // [8][3][16]
    __half* Ah    = (__half*)(smem + OFF_SEG2);           // 96 x 72

    int t = threadIdx.x;
    int warp = t >> 5;
    int box0 = blockIdx.x * 32;

    // ---- weight fills (complete before GEMM1; pool syncs cover ordering)
    for (int i = t; i < 1088; i += 512) ((uint4*)w1h)[i] = ((const uint4*)g_w1h)[i];
    for (int i = t; i < 1152; i += 512) ((uint4*)w2h)[i] = ((const uint4*)g_w2h)[i];
    for (int i = t; i < 4352; i += 512) ((uint4*)p1h)[i] = ((const uint4*)g_p1h)[i];
    for (int i = t; i < 1152; i += 512) ((uint4*)p2h)[i] = ((const uint4*)g_p2h)[i];

    // ---- pool: 4 rounds x 8 boxes; 64 thr/box = 4 corners x 16 chunks
    int slot = t >> 6;          // 0..7
    int tid = t & 63;
    for (int q = 0; q < 4; q++) {
        int lb = q * 8 + slot;                // local box 0..31
        int box = box0 + lb;

        float x1 = boxes[box * 4 + 0] * (2.0f / 960.0f) - 1.0f;
        float y1 = boxes[box * 4 + 1] * (2.0f / 960.0f) - 1.0f;
        float x2 = boxes[box * 4 + 2] * (2.0f / 960.0f) - 1.0f;
        float y2 = boxes[box * 4 + 3] * (2.0f / 960.0f) - 1.0f;
        float cx = 0.5f * (x1 + x2), cy = 0.5f * (y1 + y2);
        float bw2 = 0.5f * fmaxf(x2 - x1, 1e-6f);
        float bh2 = 0.5f * fmaxf(y2 - y1, 1e-6f);

        int*   offp = s_off + slot * (4 * NSAMP);
        float* wp   = s_w   + slot * (4 * NSAMP);

        for (int i = tid; i < NSAMP; i += 64) {
            int r, j;
            if (i < 9)       { r = 3;  j = i; }
            else if (i < 58) { r = 7;  j = i - 9; }
            else             { r = 11; j = i - 58; }
            int sy = j / r, sx = j - sy * r;
            float invr = 1.0f / (float)r;
            float liny = (2.0f * sy + 1.0f) * invr - 1.0f;
            float linx = (2.0f * sx + 1.0f) * invr - 1.0f;
            float gy = cy + bh2 * liny;
            float gx = cx + bw2 * linx;
            float iy = ((gy + 1.0f) * (float)HH - 1.0f) * 0.5f;
            float ix = ((gx + 1.0f) * (float)WW - 1.0f) * 0.5f;
            float y0f = floorf(iy), x0f = floorf(ix);
            float wy1 = iy - y0f, wx1 = ix - x0f;
            int y0 = (int)y0f, x0 = (int)x0f;
            int y1i = y0 + 1, x1i = x0 + 1;
            float vx0 = (x0 >= 0 && x0 < WW) ? 1.f : 0.f;
            float vx1 = (x1i >= 0 && x1i < WW) ? 1.f : 0.f;
            float vy0 = (y0 >= 0 && y0 < HH) ? 1.f : 0.f;
            float vy1 = (y1i >= 0 && y1i < HH) ? 1.f : 0.f;
            int x0c = min(max(x0, 0), WW - 1);
            int x1c = min(max(x1i, 0), WW - 1);
            int y0c = min(max(y0, 0), HH - 1);
            int y1c = min(max(y1i, 0), HH - 1);
            offp[0 * NSAMP + i] = (y0c * WW + x0c) * 64;
            offp[1 * NSAMP + i] = (y0c * WW + x1c) * 64;
            offp[2 * NSAMP + i] = (y1c * WW + x0c) * 64;
            offp[3 * NSAMP + i] = (y1c * WW + x1c) * 64;
            wp[0 * NSAMP + i] = (1.f - wx1) * (1.f - wy1) * vx0 * vy0;
            wp[1 * NSAMP + i] = wx1 * (1.f - wy1) * vx1 * vy0;
            wp[2 * NSAMP + i] = (1.f - wx1) * wy1 * vx0 * vy1;
            wp[3 * NSAMP + i] = wx1 * wy1 * vx1 * vy1;
        }
        __syncthreads();

        int corner = tid >> 4, chunk = tid & 15;
        const int*   off = offp + corner * NSAMP;
        const float* wts = wp + corner * NSAMP;
        float4 a0 = make_float4(0.f, 0.f, 0.f, 0.f);
        float4 a1 = a0, a2 = a0;

#define SAMPLE(ACC, I) { \
        int o = off[I] + chunk * 4; \
        uint2 u = *reinterpret_cast<const uint2*>(&g_fm_h[o]); \
        __half2 h01 = *reinterpret_cast<__half2*>(&u.x); \
        __half2 h23 = *reinterpret_cast<__half2*>(&u.y); \
        float2 f01 = __half22float2(h01); \
        float2 f23 = __half22float2(h23); \
        float w = wts[I]; \
        ACC.x = fmaf(f01.x, w, ACC.x); \
        ACC.y = fmaf(f01.y, w, ACC.y); \
        ACC.z = fmaf(f23.x, w, ACC.z); \
        ACC.w = fmaf(f23.y, w, ACC.w); }

        #pragma unroll 3
        for (int i = 0; i < 9; i++)    SAMPLE(a0, i)
        #pragma unroll 7
        for (int i = 9; i < 58; i++)   SAMPLE(a1, i)
        #pragma unroll 11
        for (int i = 58; i < NSAMP; i++) SAMPLE(a2, i)
#undef SAMPLE

#define RED4(V) { \
        V.x += __shfl_xor_sync(0xffffffffu, V.x, 16); \
        V.y += __shfl_xor_sync(0xffffffffu, V.y, 16); \
        V.z += __shfl_xor_sync(0xffffffffu, V.z, 16); \
        V.w += __shfl_xor_sync(0xffffffffu, V.w, 16); }
        RED4(a0) RED4(a1) RED4(a2)
#undef RED4

        if (tid >= 32 && tid < 48) {     // corners 2+3 partial
            s_red[(slot * 3 + 0) * 16 + chunk] = a0;
            s_red[(slot * 3 + 1) * 16 + chunk] = a1;
            s_red[(slot * 3 + 2) * 16 + chunk] = a2;
        }
        __syncthreads();
        if (tid < 16) {                  // corners 0+1; add, scale, write Ah fp16
            float4 r0 = s_red[(slot * 3 + 0) * 16 + chunk];
            float4 r1 = s_red[(slot * 3 + 1) * 16 + chunk];
            float4 r2 = s_red[(slot * 3 + 2) * 16 + chunk];
            __half2 v0a = __floats2half2_rn((a0.x + r0.x) * (1.f/9.f),  (a0.y + r0.y) * (1.f/9.f));
            __half2 v0b = __floats2half2_rn((a0.z + r0.z) * (1.f/9.f),  (a0.w + r0.w) * (1.f/9.f));
            __half2 v1a = __floats2half2_rn((a1.x + r1.x) * (1.f/49.f), (a1.y + r1.y) * (1.f/49.f));
            __half2 v1b = __floats2half2_rn((a1.z + r1.z) * (1.f/49.f), (a1.w + r1.w) * (1.f/49.f));
            __half2 v2a = __floats2half2_rn((a2.x + r2.x) * (1.f/121.f),(a2.y + r2.y) * (1.f/121.f));
            __half2 v2b = __floats2half2_rn((a2.z + r2.z) * (1.f/121.f),(a2.w + r2.w) * (1.f/121.f));
            *reinterpret_cast<uint2*>(&Ah[(0 * 32 + lb) * 72 + chunk * 4]) =
                make_uint2(*(unsigned*)&v0a, *(unsigned*)&v0b);
            *reinterpret_cast<uint2*>(&Ah[(1 * 32 + lb) * 72 + chunk * 4]) =
                make_uint2(*(unsigned*)&v1a, *(unsigned*)&v1b);
            *reinterpret_cast<uint2*>(&Ah[(2 * 32 + lb) * 72 + chunk * 4]) =
                make_uint2(*(unsigned*)&v2a, *(unsigned*)&v2b);
        }
        __syncthreads();
    }

    // ---- GEMM1: Ah[96x64] @ w1h[64x128] -> h1f[96x132]
    float* h1f = (float*)(smem + OFF_SEG1);
    for (int tt = warp; tt < 48; tt += 16) {
        int mt = tt >> 3, nt = tt & 7;
        wmma::fragment<wmma::accumulator, 16, 16, 16, float> cf;
        wmma::fill_fragment(cf, 0.f);
        #pragma unroll
        for (int k = 0; k < 4; k++) {
            wmma::fragment<wmma::matrix_a, 16, 16, 16, __half, wmma::row_major> af;
            wmma::fragment<wmma::matrix_b, 16, 16, 16, __half, wmma::row_major> bf;
            wmma::load_matrix_sync(af, Ah + mt * 16 * 72 + k * 16, 72);
            wmma::load_matrix_sync(bf, w1h + k * 16 * 136 + nt * 16, 136);
            wmma::mma_sync(cf, af, bf, cf);
        }
        wmma::store_matrix_sync(h1f + mt * 16 * 132 + nt * 16, cf, 132, wmma::mem_row_major);
    }
    __syncthreads();

    // ---- bias + relu -> h1h[96x136] (SEG2; Ah dead)
    __half* h1h = (__half*)(smem + OFF_SEG2);
    for (int i = t; i < 96 * 128; i += 512) {
        int r = i >> 7, c = i & 127;
        h1h[r * 136 + c] = __float2half_rn(fmaxf(h1f[r * 132 + c] + b1[c], 0.f));
    }
    __syncthreads();

    // ---- GEMM2: h1h[96x128] @ w2h[128x64] -> c2f[96x68] (SEG1; h1f dead)
    float* c2f = (float*)(smem + OFF_SEG1);
    for (int tt = warp; tt < 24; tt += 16) {
        int mt = tt >> 2, nt = tt & 3;
        wmma::fragment<wmma::accumulator, 16, 16, 16, float> cf;
        wmma::fill_fragment(cf, 0.f);
        #pragma unroll
        for (int k = 0; k < 8; k++) {
            wmma::fragment<wmma::matrix_a, 16, 16, 16, __half, wmma::row_major> af;
            wmma::fragment<wmma::matrix_b, 16, 16, 16, __half, wmma::row_major> bf;
            wmma::load_matrix_sync(af, h1h + mt * 16 * 136 + k * 16, 136);
            wmma::load_matrix_sync(bf, w2h + k * 16 * 72 + nt * 16, 72);
            wmma::mma_sync(cf, af, bf, cf);
        }
        wmma::store_matrix_sync(c2f + mt * 16 * 68 + nt * 16, cf, 68, wmma::mem_row_major);
    }
    __syncthreads();

    // ---- build concat xh[32x264] (SEG2; h1h dead): relu(c2f+b2) + gh
    __half* xh = (__half*)(smem + OFF_SEG2);
    for (int i = t; i < 96 * 64; i += 512) {
        int r = i >> 6, c = i & 63;
        int s = r >> 5, lb = r & 31;
        xh[lb * 264 + s * 64 + c] = __float2half_rn(fmaxf(c2f[r * 68 + c] + b2[c], 0.f));
    }
    for (int i = t; i < 32 * 64; i += 512) {
        int lb = i >> 6, c = i & 63;
        xh[lb * 264 + 192 + c] = g_gh_h[c];
    }
    __syncthreads();

    // ---- GEMM3: xh[32x256] @ p1h[256x128] -> h2f[32x132] (SEG1; c2f dead)
    float* h2f = (float*)(smem + OFF_SEG1);
    {
        int mt = warp >> 3, nt = warp & 7;
        wmma::fragment<wmma::accumulator, 16, 16, 16, float> cf;
        wmma::fill_fragment(cf, 0.f);
        #pragma unroll
        for (int k = 0; k < 16; k++) {
            wmma::fragment<wmma::matrix_a, 16, 16, 16, __half, wmma::row_major> af;
            wmma::fragment<wmma::matrix_b, 16, 16, 16, __half, wmma::row_major> bf;
            wmma::load_matrix_sync(af, xh + mt * 16 * 264 + k * 16, 264);
            wmma::load_matrix_sync(bf, p1h + k * 16 * 136 + nt * 16, 136);
            wmma::mma_sync(cf, af, bf, cf);
        }
        wmma::store_matrix_sync(h2f + mt * 16 * 132 + nt * 16, cf, 132, wmma::mem_row_major);
    }
    __syncthreads();

    // ---- bias + relu -> h2h[32x136] (SEG2; xh dead)
    __half* h2h = (__half*)(smem + OFF_SEG2);
    for (int i = t; i < 32 * 128; i += 512) {
        int r = i >> 7, c = i & 127;
        h2h[r * 136 + c] = __float2half_rn(fmaxf(h2f[r * 132 + c] + pb1[c], 0.f));
    }
    __syncthreads();

    // ---- GEMM4: h2h[32x128] @ p2h[128x64] -> c4f[32x68] (SEG1; h2f dead)
    float* c4f = (float*)(smem + OFF_SEG1);
    if (warp < 8) {
        int mt = warp >> 2, nt = warp & 3;
        wmma::fragment<wmma::accumulator, 16, 16, 16, float> cf;
        wmma::fill_fragment(cf, 0.f);
        #pragma unroll
        for (int k = 0; k < 8; k++) {
            wmma::fragment<wmma::matrix_a, 16, 16, 16, __half, wmma::row_major> af;
            wmma::fragment<wmma::matrix_b, 16, 16, 16, __half, wmma::row_major> bf;
            wmma::load_matrix_sync(af, h2h + mt * 16 * 136 + k * 16, 136);
            wmma::load_matrix_sync(bf, p2h + k * 16 * 72 + nt * 16, 72);
            wmma::mma_sync(cf, af, bf, cf);
        }
        wmma::store_matrix_sync(c4f + mt * 16 * 68 + nt * 16, cf, 68, wmma::mem_row_major);
    }
    __syncthreads();

    // ---- bias + relu -> out
    for (int i = t; i < 32 * 64; i += 512) {
        int r = i >> 6, c = i & 63;
        out[(box0 + r) * 64 + c] = fmaxf(c4f[r * 68 + c] + pb2[c], 0.f);
    }
}

extern "C" void kernel_launch(void* const* d_in, const int* in_sizes, int n_in,
                              void* d_out, int out_size) {
    const float* fm    = (const float*)d_in[0];
    const float* boxes = (const float*)d_in[1];
    const float* w1    = (const float*)d_in[2];
    const float* b1    = (const float*)d_in[3];
    const float* w2    = (const float*)d_in[4];
    const float* b2    = (const float*)d_in[5];
    const float* p1    = (const float*)d_in[6];
    const float* pb1   = (const float*)d_in[7];
    const float* p2    = (const float*)d_in[8];
    const float* pb2   = (const float*)d_in[9];
    float* out = (float*)d_out;

    cudaFuncSetAttribute(k_mega, cudaFuncAttributeMaxDynamicSharedMemorySize, SMEM_MEGA);

    k_transpose<<<NTILE, dim3(32, 8)>>>(fm);
    k_prep<<<65, 512>>>(w1, b1, w2, b2, p1, p2);
    k_mega<<<128, 512, SMEM_MEGA>>>(boxes, b1, b2, pb1, pb2, out);
}

// round 7
// speedup vs baseline: 1.3343x; 1.3343x over previous
#include <cuda_runtime.h>
#include <cuda_fp16.h>
#include <mma.h>
using namespace nvcuda;

#define CCH 64
#define HH 120
#define WW 120
#define NBOX 4096
#define NPIX (HH*WW)
#define NSAMP 179      // 9 + 49 + 121
#define NTILE 450      // NPIX / 32

__device__ __half g_fm_h[NPIX * CCH];       // fp16 HWC feature map
__device__ float  g_part[NTILE * CCH];      // per-tile channel partial sums

// padded fp16 weights (conflict-free ldm)
__device__ __half g_w1h[64 * 136];
__device__ __half g_w2h[128 * 72];
__device__ __half g_p1h[256 * 136];
__device__ __half g_p2h[128 * 72];

// ---- cp.async helpers ----
__device__ __forceinline__ void cp16(void* d, const void* s) {
    unsigned u = (unsigned)__cvta_generic_to_shared(d);
    asm volatile("cp.async.cg.shared.global [%0], [%1], 16;" :: "r"(u), "l"(s));
}
__device__ __forceinline__ void cp4(void* d, const void* s) {
    unsigned u = (unsigned)__cvta_generic_to_shared(d);
    asm volatile("cp.async.ca.shared.global [%0], [%1], 4;" :: "r"(u), "l"(s));
}

// ---------------------------------------------------------------- PRE: transpose (blocks 0..449) + weight convert (450..513)
__global__ void k_pre(const float* __restrict__ fm,
                      const float* __restrict__ w1, const float* __restrict__ w2,
                      const float* __restrict__ p1, const float* __restrict__ p2) {
    __shared__ float s[64][33];
    int tx = threadIdx.x, ty = threadIdx.y;          // (32, 8)
    int t = ty * 32 + tx;

    if (blockIdx.x >= 450) {
        int tid = (blockIdx.x - 450) * 256 + t;
        const int nt = 64 * 256;
        for (int i = tid; i < 8192; i += nt)  g_w1h[(i >> 7) * 136 + (i & 127)] = __float2half_rn(w1[i]);
        for (int i = tid; i < 8192; i += nt)  g_w2h[(i >> 6) * 72  + (i & 63)]  = __float2half_rn(w2[i]);
        for (int i = tid; i < 32768; i += nt) g_p1h[(i >> 7) * 136 + (i & 127)] = __float2half_rn(p1[i]);
        for (int i = tid; i < 8192; i += nt)  g_p2h[(i >> 6) * 72  + (i & 63)]  = __float2half_rn(p2[i]);
        return;
    }

    int pix0 = blockIdx.x * 32;
    #pragma unroll
    for (int c = ty; c < 64; c += 8)
        cp4(&s[c][tx], &fm[c * NPIX + pix0 + tx]);
    asm volatile("cp.async.commit_group;");
    asm volatile("cp.async.wait_group 0;");
    __syncthreads();

    int p = t >> 3;
    int c0 = (t & 7) * 8;
    __half h[8];
    #pragma unroll
    for (int k = 0; k < 8; k++) h[k] = __float2half_rn(s[c0 + k][p]);
    *reinterpret_cast<uint4*>(&g_fm_h[(pix0 + p) * 64 + c0]) = *reinterpret_cast<uint4*>(h);

    int c = t >> 2, q = t & 3;
    float v = 0.f;
    #pragma unroll
    for (int j = 0; j < 8; j++) v += s[c][q * 8 + j];
    v += __shfl_xor_sync(0xffffffffu, v, 1);
    v += __shfl_xor_sync(0xffffffffu, v, 2);
    if (q == 0) g_part[blockIdx.x * 64 + c] = v;
}

// ---------------------------------------------------------------- MEGA
// smem (bytes):
//   w1h @0 (17408) | w2h @17408 (18432) | p1h @35840 (69632) | p2h @105472 (18432)
//   bsh @123904 (1536: b1[128],b2[64],pb1[128],pb2[64] fl) | ghs @125440 (128: 64 half)
//   SEG1 @125568 (51968): pool meta 8x5728 + sred 6144  ->  h1f 96x132f -> c2f 96x68f -> h2f -> c4f
//   SEG2 @177536 (26112): gh scratch -> Ah 96x72h -> h1h 96x136h -> xh 32x264h -> h2h 32x136h
#define OFF_W1H 0
#define OFF_W2H 17408
#define OFF_P1H 35840
#define OFF_P2H 105472
#define OFF_BSH 123904
#define OFF_GHS 125440
#define OFF_SEG1 125568
#define OFF_SEG2 177536
#define SMEM_MEGA 203648

__global__ void __launch_bounds__(512, 1)
k_mega(const float* __restrict__ boxes,
       const float* __restrict__ w1, const float* __restrict__ b1,
       const float* __restrict__ w2, const float* __restrict__ b2,
       const float* __restrict__ pb1, const float* __restrict__ pb2,
       float* __restrict__ out) {
    extern __shared__ char smem[];
    __half* w1h = (__half*)(smem + OFF_W1H);
    __half* w2h = (__half*)(smem + OFF_W2H);
    __half* p1h = (__half*)(smem + OFF_P1H);
    __half* p2h = (__half*)(smem + OFF_P2H);
    float*  bsh = (float*)(smem + OFF_BSH);
    __half* ghs = (__half*)(smem + OFF_GHS);

    int t = threadIdx.x;
    int warp = t >> 5;
    int box0 = blockIdx.x * 32;

    // ---- async weight + bias fills (overlap with gh + pool)
    for (int i = t; i < 1088; i += 512) cp16((uint4*)w1h + i, (const uint4*)g_w1h + i);
    for (int i = t; i < 1152; i += 512) cp16((uint4*)w2h + i, (const uint4*)g_w2h + i);
    for (int i = t; i < 4352; i += 512) cp16((uint4*)p1h + i, (const uint4*)g_p1h + i);
    for (int i = t; i < 1152; i += 512) cp16((uint4*)p2h + i, (const uint4*)g_p2h + i);
    if (t < 32)                cp16((uint4*)bsh + t,             (const uint4*)b1  + t);
    else if (t < 48)           cp16((uint4*)bsh + 32 + (t - 32), (const uint4*)b2  + (t - 32));
    else if (t >= 64 && t < 96)  cp16((uint4*)bsh + 48 + (t - 64), (const uint4*)pb1 + (t - 64));
    else if (t >= 96 && t < 112) cp16((uint4*)bsh + 80 + (t - 96), (const uint4*)pb2 + (t - 96));
    asm volatile("cp.async.commit_group;");

    // ---- global-branch head (fp32, per-block redundant; scratch in SEG2)
    {
        float* gsc  = (float*)(smem + OFF_SEG2);          // 2048 fl
        float* psum = (float*)(smem + OFF_SEG2 + 8192);   // 256 fl
        float* gs   = (float*)(smem + OFF_SEG2 + 9216);   // 64 fl
        float* red  = (float*)(smem + OFF_SEG2 + 9472);   // 512 fl
        float* hs   = (float*)(smem + OFF_SEG2 + 11520);  // 128 fl

        float4 a = make_float4(0.f, 0.f, 0.f, 0.f);
        const float4* gp4 = (const float4*)g_part;        // 7200
        for (int i = t; i < 7200; i += 512) {
            float4 v = gp4[i];
            a.x += v.x; a.y += v.y; a.z += v.z; a.w += v.w;
        }
        ((float4*)gsc)[t] = a;
        __syncthreads();
        if (t < 256) {
            int c = t & 63, hh = t >> 6;
            float s = 0.f;
            #pragma unroll
            for (int g = 0; g < 8; g++) s += gsc[(hh + g * 4) * 64 + c];
            psum[t] = s;
        }
        __syncthreads();
        if (t < 64)
            gs[t] = (psum[t] + psum[t + 64] + psum[t + 128] + psum[t + 192]) * (1.0f / (float)NPIX);
        __syncthreads();
        {   // layer 1: 128 neurons x 4 threads
            int n = t >> 2, k0 = (t & 3) * 16;
            float acc = 0.f;
            #pragma unroll
            for (int k = 0; k < 16; k++) acc = fmaf(gs[k0 + k], w1[(k0 + k) * 128 + n], acc);
            red[t] = acc;
        }
        __syncthreads();
        if (t < 128)
            hs[t] = fmaxf(red[t * 4] + red[t * 4 + 1] + red[t * 4 + 2] + red[t * 4 + 3] + b1[t], 0.f);
        __syncthreads();
        {   // layer 2: 64 neurons x 8 threads
            int n = t >> 3, k0 = (t & 7) * 16;
            float acc = 0.f;
            #pragma unroll
            for (int k = 0; k < 16; k++) acc = fmaf(hs[k0 + k], w2[(k0 + k) * 64 + n], acc);
            red[t] = acc;
        }
        __syncthreads();
        if (t < 64) {
            float s = 0.f;
            #pragma unroll
            for (int q = 0; q < 8; q++) s += red[t * 8 + q];
            ghs[t] = __float2half_rn(fmaxf(s + b2[t], 0.f));
        }
        __syncthreads();   // SEG2 scratch dead; pool may now write Ah
    }

    // ---- pool: 8 slots x 64 thr, named-barrier local, 4 rounds
    __half* Ah = (__half*)(smem + OFF_SEG2);              // 96 x 72 halves
    {
        int slot = t >> 6;
        int tid = t & 63;
        int corner = tid >> 4, chunk = tid & 15;
        char*   meta = smem + OFF_SEG1 + slot * 5728;     // [4][179] x {int off, float w}
        float4* sred = (float4*)(smem + OFF_SEG1 + 45824) + slot * 48;
        const char* fmb = (const char*)g_fm_h + chunk * 8;
        int barid = 1 + slot;

        for (int q = 0; q < 4; q++) {
            int lb = q * 8 + slot;
            int box = box0 + lb;

            float x1 = boxes[box * 4 + 0] * (2.0f / 960.0f) - 1.0f;
            float y1 = boxes[box * 4 + 1] * (2.0f / 960.0f) - 1.0f;
            float x2 = boxes[box * 4 + 2] * (2.0f / 960.0f) - 1.0f;
            float y2 = boxes[box * 4 + 3] * (2.0f / 960.0f) - 1.0f;
            float cx = 0.5f * (x1 + x2), cy = 0.5f * (y1 + y2);
            float bw2 = 0.5f * fmaxf(x2 - x1, 1e-6f);
            float bh2 = 0.5f * fmaxf(y2 - y1, 1e-6f);

            for (int i = tid; i < NSAMP; i += 64) {
                int r, j;
                if (i < 9)       { r = 3;  j = i; }
                else if (i < 58) { r = 7;  j = i - 9; }
                else             { r = 11; j = i - 58; }
                int sy = j / r, sx = j - sy * r;
                float invr = 1.0f / (float)r;
                float liny = (2.0f * sy + 1.0f) * invr - 1.0f;
                float linx = (2.0f * sx + 1.0f) * invr - 1.0f;
                float gy = cy + bh2 * liny;
                float gx = cx + bw2 * linx;
                float iy = ((gy + 1.0f) * (float)HH - 1.0f) * 0.5f;
                float ix = ((gx + 1.0f) * (float)WW - 1.0f) * 0.5f;
                float y0f = floorf(iy), x0f = floorf(ix);
                float wy1 = iy - y0f, wx1 = ix - x0f;
                int y0 = (int)y0f, x0 = (int)x0f;
                int y1i = y0 + 1, x1i = x0 + 1;
                float vx0 = (x0 >= 0 && x0 < WW) ? 1.f : 0.f;
                float vx1 = (x1i >= 0 && x1i < WW) ? 1.f : 0.f;
                float vy0 = (y0 >= 0 && y0 < HH) ? 1.f : 0.f;
                float vy1 = (y1i >= 0 && y1i < HH) ? 1.f : 0.f;
                int x0c = min(max(x0, 0), WW - 1);
                int x1c = min(max(x1i, 0), WW - 1);
                int y0c = min(max(y0, 0), HH - 1);
                int y1c = min(max(y1i, 0), HH - 1);
                ((int2*)(meta + 0 * 1432))[i] = make_int2((y0c * WW + x0c) * 128,
                    __float_as_int((1.f - wx1) * (1.f - wy1) * vx0 * vy0));
                ((int2*)(meta + 1 * 1432))[i] = make_int2((y0c * WW + x1c) * 128,
                    __float_as_int(wx1 * (1.f - wy1) * vx1 * vy0));
                ((int2*)(meta + 2 * 1432))[i] = make_int2((y1c * WW + x0c) * 128,
                    __float_as_int((1.f - wx1) * wy1 * vx0 * vy1));
                ((int2*)(meta + 3 * 1432))[i] = make_int2((y1c * WW + x1c) * 128,
                    __float_as_int(wx1 * wy1 * vx1 * vy1));
            }
            asm volatile("bar.sync %0, 64;" :: "r"(barid) : "memory");

            const int2* mp = (const int2*)(meta + corner * 1432);
            float4 a0 = make_float4(0.f, 0.f, 0.f, 0.f);
            float4 a1 = a0, a2 = a0;

#define SAMPLE(ACC, I) { \
            int2 pw = mp[I]; \
            uint2 u = *reinterpret_cast<const uint2*>(fmb + pw.x); \
            float w = __int_as_float(pw.y); \
            __half2 h01 = *reinterpret_cast<__half2*>(&u.x); \
            __half2 h23 = *reinterpret_cast<__half2*>(&u.y); \
            float2 f01 = __half22float2(h01); \
            float2 f23 = __half22float2(h23); \
            ACC.x = fmaf(f01.x, w, ACC.x); \
            ACC.y = fmaf(f01.y, w, ACC.y); \
            ACC.z = fmaf(f23.x, w, ACC.z); \
            ACC.w = fmaf(f23.y, w, ACC.w); }

            #pragma unroll 3
            for (int i = 0; i < 9; i++)      SAMPLE(a0, i)
            #pragma unroll 7
            for (int i = 9; i < 58; i++)     SAMPLE(a1, i)
            #pragma unroll 11
            for (int i = 58; i < NSAMP; i++) SAMPLE(a2, i)
#undef SAMPLE

#define RED4(V) { \
            V.x += __shfl_xor_sync(0xffffffffu, V.x, 16); \
            V.y += __shfl_xor_sync(0xffffffffu, V.y, 16); \
            V.z += __shfl_xor_sync(0xffffffffu, V.z, 16); \
            V.w += __shfl_xor_sync(0xffffffffu, V.w, 16); }
            RED4(a0) RED4(a1) RED4(a2)
#undef RED4

            if (tid >= 32 && tid < 48) {     // corners 2+3 partial
                sred[0 * 16 + chunk] = a0;
                sred[1 * 16 + chunk] = a1;
                sred[2 * 16 + chunk] = a2;
            }
            asm volatile("bar.sync %0, 64;" :: "r"(barid) : "memory");
            if (tid < 16) {
                float4 r0 = sred[0 * 16 + chunk];
                float4 r1 = sred[1 * 16 + chunk];
                float4 r2 = sred[2 * 16 + chunk];
                __half2 v0a = __floats2half2_rn((a0.x + r0.x) * (1.f/9.f),  (a0.y + r0.y) * (1.f/9.f));
                __half2 v0b = __floats2half2_rn((a0.z + r0.z) * (1.f/9.f),  (a0.w + r0.w) * (1.f/9.f));
                __half2 v1a = __floats2half2_rn((a1.x + r1.x) * (1.f/49.f), (a1.y + r1.y) * (1.f/49.f));
                __half2 v1b = __floats2half2_rn((a1.z + r1.z) * (1.f/49.f), (a1.w + r1.w) * (1.f/49.f));
                __half2 v2a = __floats2half2_rn((a2.x + r2.x) * (1.f/121.f),(a2.y + r2.y) * (1.f/121.f));
                __half2 v2b = __floats2half2_rn((a2.z + r2.z) * (1.f/121.f),(a2.w + r2.w) * (1.f/121.f));
                *reinterpret_cast<uint2*>(&Ah[(0 * 32 + lb) * 72 + chunk * 4]) =
                    make_uint2(*(unsigned*)&v0a, *(unsigned*)&v0b);
                *reinterpret_cast<uint2*>(&Ah[(1 * 32 + lb) * 72 + chunk * 4]) =
                    make_uint2(*(unsigned*)&v1a, *(unsigned*)&v1b);
                *reinterpret_cast<uint2*>(&Ah[(2 * 32 + lb) * 72 + chunk * 4]) =
                    make_uint2(*(unsigned*)&v2a, *(unsigned*)&v2b);
            }
        }
    }

    asm volatile("cp.async.wait_group 0;");
    __syncthreads();

    // ---- GEMM1: Ah[96x64] @ w1h[64x128] -> h1f[96x132]
    float* h1f = (float*)(smem + OFF_SEG1);
    for (int tt = warp; tt < 48; tt += 16) {
        int mt = tt >> 3, nt = tt & 7;
        wmma::fragment<wmma::accumulator, 16, 16, 16, float> cf;
        wmma::fill_fragment(cf, 0.f);
        #pragma unroll
        for (int k = 0; k < 4; k++) {
            wmma::fragment<wmma::matrix_a, 16, 16, 16, __half, wmma::row_major> af;
            wmma::fragment<wmma::matrix_b, 16, 16, 16, __half, wmma::row_major> bf;
            wmma::load_matrix_sync(af, Ah + mt * 16 * 72 + k * 16, 72);
            wmma::load_matrix_sync(bf, w1h + k * 16 * 136 + nt * 16, 136);
            wmma::mma_sync(cf, af, bf, cf);
        }
        wmma::store_matrix_sync(h1f + mt * 16 * 132 + nt * 16, cf, 132, wmma::mem_row_major);
    }
    __syncthreads();

    // ---- bias + relu -> h1h[96x136] (SEG2; Ah dead)
    __half* h1h = (__half*)(smem + OFF_SEG2);
    for (int i = t; i < 96 * 128; i += 512) {
        int r = i >> 7, c = i & 127;
        h1h[r * 136 + c] = __float2half_rn(fmaxf(h1f[r * 132 + c] + bsh[c], 0.f));
    }
    __syncthreads();

    // ---- GEMM2: h1h[96x128] @ w2h[128x64] -> c2f[96x68]
    float* c2f = (float*)(smem + OFF_SEG1);
    for (int tt = warp; tt < 24; tt += 16) {
        int mt = tt >> 2, nt = tt & 3;
        wmma::fragment<wmma::accumulator, 16, 16, 16, float> cf;
        wmma::fill_fragment(cf, 0.f);
        #pragma unroll
        for (int k = 0; k < 8; k++) {
            wmma::fragment<wmma::matrix_a, 16, 16, 16, __half, wmma::row_major> af;
            wmma::fragment<wmma::matrix_b, 16, 16, 16, __half, wmma::row_major> bf;
            wmma::load_matrix_sync(af, h1h + mt * 16 * 136 + k * 16, 136);
            wmma::load_matrix_sync(bf, w2h + k * 16 * 72 + nt * 16, 72);
            wmma::mma_sync(cf, af, bf, cf);
        }
        wmma::store_matrix_sync(c2f + mt * 16 * 68 + nt * 16, cf, 68, wmma::mem_row_major);
    }
    __syncthreads();

    // ---- build concat xh[32x264] (SEG2; h1h dead)
    __half* xh = (__half*)(smem + OFF_SEG2);
    for (int i = t; i < 96 * 64; i += 512) {
        int r = i >> 6, c = i & 63;
        int s = r >> 5, lb = r & 31;
        xh[lb * 264 + s * 64 + c] = __float2half_rn(fmaxf(c2f[r * 68 + c] + bsh[128 + c], 0.f));
    }
    for (int i = t; i < 32 * 64; i += 512) {
        int lb = i >> 6, c = i & 63;
        xh[lb * 264 + 192 + c] = ghs[c];
    }
    __syncthreads();

    // ---- GEMM3: xh[32x256] @ p1h[256x128] -> h2f[32x132]
    float* h2f = (float*)(smem + OFF_SEG1);
    {
        int mt = warp >> 3, nt = warp & 7;
        wmma::fragment<wmma::accumulator, 16, 16, 16, float> cf;
        wmma::fill_fragment(cf, 0.f);
        #pragma unroll
        for (int k = 0; k < 16; k++) {
            wmma::fragment<wmma::matrix_a, 16, 16, 16, __half, wmma::row_major> af;
            wmma::fragment<wmma::matrix_b, 16, 16, 16, __half, wmma::row_major> bf;
            wmma::load_matrix_sync(af, xh + mt * 16 * 264 + k * 16, 264);
            wmma::load_matrix_sync(bf, p1h + k * 16 * 136 + nt * 16, 136);
            wmma::mma_sync(cf, af, bf, cf);
        }
        wmma::store_matrix_sync(h2f + mt * 16 * 132 + nt * 16, cf, 132, wmma::mem_row_major);
    }
    __syncthreads();

    // ---- bias + relu -> h2h[32x136]
    __half* h2h = (__half*)(smem + OFF_SEG2);
    for (int i = t; i < 32 * 128; i += 512) {
        int r = i >> 7, c = i & 127;
        h2h[r * 136 + c] = __float2half_rn(fmaxf(h2f[r * 132 + c] + bsh[192 + c], 0.f));
    }
    __syncthreads();

    // ---- GEMM4: h2h[32x128] @ p2h[128x64] -> c4f[32x68]
    float* c4f = (float*)(smem + OFF_SEG1);
    if (warp < 8) {
        int mt = warp >> 2, nt = warp & 3;
        wmma::fragment<wmma::accumulator, 16, 16, 16, float> cf;
        wmma::fill_fragment(cf, 0.f);
        #pragma unroll
        for (int k = 0; k < 8; k++) {
            wmma::fragment<wmma::matrix_a, 16, 16, 16, __half, wmma::row_major> af;
            wmma::fragment<wmma::matrix_b, 16, 16, 16, __half, wmma::row_major> bf;
            wmma::load_matrix_sync(af, h2h + mt * 16 * 136 + k * 16, 136);
            wmma::load_matrix_sync(bf, p2h + k * 16 * 72 + nt * 16, 72);
            wmma::mma_sync(cf, af, bf, cf);
        }
        wmma::store_matrix_sync(c4f + mt * 16 * 68 + nt * 16, cf, 68, wmma::mem_row_major);
    }
    __syncthreads();

    for (int i = t; i < 32 * 64; i += 512) {
        int r = i >> 6, c = i & 63;
        out[(box0 + r) * 64 + c] = fmaxf(c4f[r * 68 + c] + bsh[320 + c], 0.f);
    }
}

extern "C" void kernel_launch(void* const* d_in, const int* in_sizes, int n_in,
                              void* d_out, int out_size) {
    const float* fm    = (const float*)d_in[0];
    const float* boxes = (const float*)d_in[1];
    const float* w1    = (const float*)d_in[2];
    const float* b1    = (const float*)d_in[3];
    const float* w2    = (const float*)d_in[4];
    const float* b2    = (const float*)d_in[5];
    const float* p1    = (const float*)d_in[6];
    const float* pb1   = (const float*)d_in[7];
    const float* p2    = (const float*)d_in[8];
    const float* pb2   = (const float*)d_in[9];
    float* out = (float*)d_out;

    cudaFuncSetAttribute(k_mega, cudaFuncAttributeMaxDynamicSharedMemorySize, SMEM_MEGA);

    k_pre<<<514, dim3(32, 8)>>>(fm, w1, w2, p1, p2);
    k_mega<<<128, 512, SMEM_MEGA>>>(boxes, w1, b1, w2, b2, pb1, pb2, out);
}